// round 5
// baseline (speedup 1.0000x reference)
#include <cuda_runtime.h>
#include <cuda_bf16.h>
#include <cstdint>

// SeparationLoss: mean over B of sum_{i!=j} max(0, thr2 - ||kp_i - kp_j||^2)
// Input: batched_kps [B, 17, 3] f32 (B = 131072). Output: scalar f32.
//
// R5: 64-thr/64-row blocks (one wave @ 14 blocks/SM). Tile staging via a
// single cp.async.bulk per block (removes front-batched LDGs -> kills the
// cross-CTA L1tex-queue spread). Final reduction vectorized (float4, fully
// unrolled -> one DRAM latency window). Fused last-block-done pattern.

#define J 17
#define ROW_F 51                  // 17*3 floats per row
#define ROWS_PER_BLOCK 64
#define THREADS 64
#define TILE_BYTES (ROWS_PER_BLOCK * ROW_F * 4)   // 13056, multiple of 16
#define NBLOCKS_MAX 8192

__device__ __align__(16) float g_partials[NBLOCKS_MAX];
__device__ unsigned int g_done_count;   // zero-init; atomicInc wrap self-resets per run

__device__ __forceinline__ uint32_t smem_u32(const void* p) {
    uint32_t a;
    asm("{ .reg .u64 t; cvta.to.shared.u64 t, %1; cvt.u32.u64 %0, t; }"
        : "=r"(a) : "l"(p));
    return a;
}

__global__ __launch_bounds__(THREADS, 14)   // regs <= 73 -> 14 blocks/SM, one wave
void sep_loss_fused(const float* __restrict__ kps, int B, int nblocks,
                    float invB, float* __restrict__ out) {
    __shared__ __align__(16) float s[ROWS_PER_BLOCK * ROW_F];   // 13056 B
    __shared__ __align__(8)  unsigned long long mbar;
    __shared__ float wsum[THREADS / 32];
    __shared__ bool  isLast;

    const int tid = threadIdx.x;
    const int rowBase = blockIdx.x * ROWS_PER_BLOCK;
    const int rowsHere = min(ROWS_PER_BLOCK, B - rowBase);

    if (rowsHere == ROWS_PER_BLOCK) {
        // ---- bulk-copy staging: one UBLKCP per block, zero per-warp LDGs ----
        const uint32_t mb = smem_u32(&mbar);
        if (tid == 0) {
            asm volatile("mbarrier.init.shared.b64 [%0], %1;"
                         :: "r"(mb), "r"(1) : "memory");
        }
        __syncthreads();   // init visible before anyone waits
        if (tid == 0) {
            asm volatile("mbarrier.arrive.expect_tx.shared.b64 _, [%0], %1;"
                         :: "r"(mb), "r"((uint32_t)TILE_BYTES) : "memory");
            asm volatile(
                "cp.async.bulk.shared::cta.global.mbarrier::complete_tx::bytes "
                "[%0], [%1], %2, [%3];"
                :: "r"(smem_u32(s)),
                   "l"(kps + (size_t)rowBase * ROW_F),
                   "r"((uint32_t)TILE_BYTES), "r"(mb)
                : "memory");
        }
        // wait phase 0 (acquire -> smem writes visible)
        {
            uint32_t done;
            asm volatile(
                "{\n\t.reg .pred p;\n\t"
                "mbarrier.try_wait.parity.acquire.cta.shared::cta.b64 p, [%1], %2;\n\t"
                "selp.b32 %0, 1, 0, p;\n\t}"
                : "=r"(done) : "r"(mb), "r"(0u) : "memory");
            if (!done) {
                asm volatile(
                    "{\n\t.reg .pred P1;\n\t"
                    "W_%=:\n\t"
                    "mbarrier.try_wait.parity.acquire.cta.shared::cta.b64 P1, [%0], %1, 0x989680;\n\t"
                    "@P1 bra.uni D_%=;\n\t"
                    "bra.uni W_%=;\n\t"
                    "D_%=:\n\t}"
                    :: "r"(mb), "r"(0u) : "memory");
            }
        }
    } else {
        // tail tile (not hit for B=131072): scalar coalesced staging
        const int n = rowsHere * ROW_F;
        const float* src = kps + (size_t)rowBase * ROW_F;
        for (int i = tid; i < n; i += THREADS) s[i] = src[i];
        __syncthreads();
    }

    // ---- per-thread row in registers: stride-51 LDS is conflict-free ----
    float a0 = 0.0f, a1 = 0.0f;
    if (tid < rowsHere) {
        float p[ROW_F];
        #pragma unroll
        for (int c = 0; c < ROW_F; c++) p[c] = s[tid * ROW_F + c];

        const float thr2 = 0.01f;   // THRESHOLD^2
        int k = 0;
        #pragma unroll
        for (int i = 0; i < J; i++) {
            #pragma unroll
            for (int j = i + 1; j < J; j++) {
                float dx = p[3 * i + 0] - p[3 * j + 0];
                float dy = p[3 * i + 1] - p[3 * j + 1];
                float dz = p[3 * i + 2] - p[3 * j + 2];
                float t  = fmaf(dx, dx, fmaf(dy, dy, fmaf(dz, dz, -thr2)));
                float h  = fmaxf(-t, 0.0f);        // FMNMX (alu pipe)
                if (k & 1) a1 += h; else a0 += h;  // 2 accumulators
                k++;
            }
        }
    }
    float acc = (a0 + a1) * 2.0f;                  // ordered pairs

    // ---- deterministic block reduction (2 warps) ----
    #pragma unroll
    for (int off = 16; off > 0; off >>= 1)
        acc += __shfl_down_sync(0xFFFFFFFFu, acc, off);
    if ((tid & 31) == 0) wsum[tid >> 5] = acc;
    __syncthreads();

    if (tid == 0) {
        g_partials[blockIdx.x] = wsum[0] + wsum[1];
        __threadfence();
        // wraps to 0 when old == nblocks-1 -> self-resetting across graph replays
        unsigned int c = atomicInc(&g_done_count, (unsigned int)(nblocks - 1));
        isLast = (c == (unsigned int)(nblocks - 1));
    }
    __syncthreads();

    // ---- last block: vectorized fixed-order final reduction ----
    if (isLast) {
        float v = 0.0f;
        const int nvec = nblocks >> 2;             // 512 for nblocks=2048
        const float4* gp = reinterpret_cast<const float4*>(g_partials);
        #pragma unroll 8
        for (int i = tid; i < nvec; i += THREADS) {   // 8 independent LDG.128/thread
            float4 f = gp[i];
            v += (f.x + f.y) + (f.z + f.w);
        }
        for (int i = (nvec << 2) + tid; i < nblocks; i += THREADS)  // tail (none @2048)
            v += g_partials[i];
        #pragma unroll
        for (int off = 16; off > 0; off >>= 1)
            v += __shfl_down_sync(0xFFFFFFFFu, v, off);
        if ((tid & 31) == 0) wsum[tid >> 5] = v;
        __syncthreads();
        if (tid == 0)
            out[0] = (wsum[0] + wsum[1]) * invB;
    }
}

extern "C" void kernel_launch(void* const* d_in, const int* in_sizes, int n_in,
                              void* d_out, int out_size) {
    const float* kps = (const float*)d_in[0];
    const int B = in_sizes[0] / ROW_F;
    const int nblocks = (B + ROWS_PER_BLOCK - 1) / ROWS_PER_BLOCK;  // 2048 for B=131072

    sep_loss_fused<<<nblocks, THREADS>>>(kps, B, nblocks, 1.0f / (float)B,
                                         (float*)d_out);
}

// round 6
// speedup vs baseline: 1.0201x; 1.0201x over previous
#include <cuda_runtime.h>
#include <cuda_bf16.h>
#include <cstdint>

// SeparationLoss: mean over B of sum_{i!=j} max(0, thr2 - ||kp_i - kp_j||^2)
// Input: batched_kps [B, 17, 3] f32 (B = 131072). Output: scalar f32.
//
// R6: 2 threads per row (A caches joints 0-7, B caches joints 8-16; cross
// pairs stream the foreign joint from SMEM via conflict-free LDS). Roles are
// per-warp -> no divergence. Regs ~38 -> 12 blocks/SM, 48 warps/SM (2.3x R5
// warp count). Bulk-copy staging + fused last-block-done reduction retained.

#define J 17
#define ROW_F 51                    // 17*3 floats per row
#define ROWS_PER_BLOCK 64
#define THREADS 128                 // 64 A-threads (warps 0-1) + 64 B-threads (2-3)
#define TILE_BYTES (ROWS_PER_BLOCK * ROW_F * 4)   // 13056
#define NBLOCKS_MAX 8192

__device__ __align__(16) float g_partials[NBLOCKS_MAX];
__device__ unsigned int g_done_count;   // zero-init; atomicInc wrap self-resets per run

__device__ __forceinline__ uint32_t smem_u32(const void* p) {
    uint32_t a;
    asm("{ .reg .u64 t; cvta.to.shared.u64 t, %1; cvt.u32.u64 %0, t; }"
        : "=r"(a) : "l"(p));
    return a;
}

// hinge accumulate for one pair
#define PAIR(xi, yi, zi, xj, yj, zj)                                   \
    {                                                                  \
        float dx = (xi) - (xj), dy = (yi) - (yj), dz = (zi) - (zj);    \
        float t  = fmaf(dx, dx, fmaf(dy, dy, fmaf(dz, dz, -0.01f)));   \
        float h  = fmaxf(-t, 0.0f);                                    \
        if (k & 1) a1 += h; else a0 += h;                              \
        k++;                                                           \
    }

#define XSPLIT 39   // cross pairs 0..38 -> A, 39..71 -> B (balances 653 vs 651)

__global__ __launch_bounds__(THREADS, 12)   // regs <= 42 -> 12 blocks/SM, 48 warps
void sep_loss_fused(const float* __restrict__ kps, int B, int nblocks,
                    float invB, float* __restrict__ out) {
    __shared__ __align__(16) float s[ROWS_PER_BLOCK * ROW_F];   // 13056 B
    __shared__ __align__(8)  unsigned long long mbar;
    __shared__ float wsum[THREADS / 32];
    __shared__ bool  isLast;

    const int tid = threadIdx.x;
    const int rowBase = blockIdx.x * ROWS_PER_BLOCK;
    const int rowsHere = min(ROWS_PER_BLOCK, B - rowBase);

    if (rowsHere == ROWS_PER_BLOCK) {
        // ---- single bulk copy per block (no per-warp LDG batching) ----
        const uint32_t mb = smem_u32(&mbar);
        if (tid == 0)
            asm volatile("mbarrier.init.shared.b64 [%0], %1;"
                         :: "r"(mb), "r"(1) : "memory");
        __syncthreads();
        if (tid == 0) {
            asm volatile("mbarrier.arrive.expect_tx.shared.b64 _, [%0], %1;"
                         :: "r"(mb), "r"((uint32_t)TILE_BYTES) : "memory");
            asm volatile(
                "cp.async.bulk.shared::cta.global.mbarrier::complete_tx::bytes "
                "[%0], [%1], %2, [%3];"
                :: "r"(smem_u32(s)), "l"(kps + (size_t)rowBase * ROW_F),
                   "r"((uint32_t)TILE_BYTES), "r"(mb)
                : "memory");
        }
        uint32_t done;
        asm volatile(
            "{\n\t.reg .pred p;\n\t"
            "mbarrier.try_wait.parity.acquire.cta.shared::cta.b64 p, [%1], %2;\n\t"
            "selp.b32 %0, 1, 0, p;\n\t}"
            : "=r"(done) : "r"(mb), "r"(0u) : "memory");
        if (!done) {
            asm volatile(
                "{\n\t.reg .pred P1;\n\t"
                "W_%=:\n\t"
                "mbarrier.try_wait.parity.acquire.cta.shared::cta.b64 P1, [%0], %1, 0x989680;\n\t"
                "@P1 bra.uni D_%=;\n\t"
                "bra.uni W_%=;\n\t"
                "D_%=:\n\t}"
                :: "r"(mb), "r"(0u) : "memory");
        }
    } else {
        const int n = rowsHere * ROW_F;
        const float* src = kps + (size_t)rowBase * ROW_F;
        for (int i = tid; i < n; i += THREADS) s[i] = src[i];
        __syncthreads();
    }

    // ---- role split: warps 0-1 = A (joints 0-7), warps 2-3 = B (joints 8-16) ----
    const bool roleA = tid < 64;
    const int row = roleA ? tid : (tid - 64);
    float a0 = 0.0f, a1 = 0.0f;
    int k = 0;

    if (row < rowsHere) {
        const float* __restrict__ rp = s + row * ROW_F;
        if (roleA) {
            float p[24];                       // joints 0..7
            #pragma unroll
            for (int c = 0; c < 24; c++) p[c] = rp[c];
            // intra-A: 28 pairs, register-only
            #pragma unroll
            for (int i = 0; i < 8; i++)
                #pragma unroll
                for (int j = i + 1; j < 8; j++)
                    PAIR(p[3*i], p[3*i+1], p[3*i+2], p[3*j], p[3*j+1], p[3*j+2]);
            // cross pairs c = i*9 + jj, c < XSPLIT (j-joint streamed from SMEM)
            #pragma unroll
            for (int i = 0; i < 8; i++)
                #pragma unroll
                for (int jj = 0; jj < 9; jj++) {
                    if (i * 9 + jj < XSPLIT) {
                        float xj = rp[24 + 3*jj], yj = rp[24 + 3*jj + 1],
                              zj = rp[24 + 3*jj + 2];
                        PAIR(p[3*i], p[3*i+1], p[3*i+2], xj, yj, zj);
                    }
                }
        } else {
            float p[27];                       // joints 8..16
            #pragma unroll
            for (int c = 0; c < 27; c++) p[c] = rp[24 + c];
            // intra-B: 36 pairs, register-only
            #pragma unroll
            for (int i = 0; i < 9; i++)
                #pragma unroll
                for (int j = i + 1; j < 9; j++)
                    PAIR(p[3*i], p[3*i+1], p[3*i+2], p[3*j], p[3*j+1], p[3*j+2]);
            // cross pairs c >= XSPLIT (i-joint streamed from SMEM)
            #pragma unroll
            for (int i = 0; i < 8; i++)
                #pragma unroll
                for (int jj = 0; jj < 9; jj++) {
                    if (i * 9 + jj >= XSPLIT) {
                        float xi = rp[3*i], yi = rp[3*i + 1], zi = rp[3*i + 2];
                        PAIR(xi, yi, zi, p[3*jj], p[3*jj+1], p[3*jj+2]);
                    }
                }
        }
    }
    float acc = (a0 + a1) * 2.0f;              // ordered pairs

    // ---- deterministic block reduction (4 warps) ----
    #pragma unroll
    for (int off = 16; off > 0; off >>= 1)
        acc += __shfl_down_sync(0xFFFFFFFFu, acc, off);
    if ((tid & 31) == 0) wsum[tid >> 5] = acc;
    __syncthreads();

    if (tid == 0) {
        g_partials[blockIdx.x] = (wsum[0] + wsum[1]) + (wsum[2] + wsum[3]);
        __threadfence();
        // wraps to 0 when old == nblocks-1 -> self-resetting across graph replays
        unsigned int c = atomicInc(&g_done_count, (unsigned int)(nblocks - 1));
        isLast = (c == (unsigned int)(nblocks - 1));
    }
    __syncthreads();

    // ---- last block: vectorized fixed-order final reduction ----
    if (isLast) {
        float v = 0.0f;
        const int nvec = nblocks >> 2;
        const float4* gp = reinterpret_cast<const float4*>(g_partials);
        #pragma unroll 4
        for (int i = tid; i < nvec; i += THREADS) {
            float4 f = gp[i];
            v += (f.x + f.y) + (f.z + f.w);
        }
        for (int i = (nvec << 2) + tid; i < nblocks; i += THREADS)
            v += g_partials[i];
        #pragma unroll
        for (int off = 16; off > 0; off >>= 1)
            v += __shfl_down_sync(0xFFFFFFFFu, v, off);
        if ((tid & 31) == 0) wsum[tid >> 5] = v;
        __syncthreads();
        if (tid == 0)
            out[0] = ((wsum[0] + wsum[1]) + (wsum[2] + wsum[3])) * invB;
    }
}

extern "C" void kernel_launch(void* const* d_in, const int* in_sizes, int n_in,
                              void* d_out, int out_size) {
    const float* kps = (const float*)d_in[0];
    const int B = in_sizes[0] / ROW_F;
    const int nblocks = (B + ROWS_PER_BLOCK - 1) / ROWS_PER_BLOCK;  // 2048

    sep_loss_fused<<<nblocks, THREADS>>>(kps, B, nblocks, 1.0f / (float)B,
                                         (float*)d_out);
}